// round 8
// baseline (speedup 1.0000x reference)
#include <cuda_runtime.h>
#include <cuda_fp16.h>
#include <cstdint>

// Q4_0 dequant GEMM via mma.sync (HMMA) fp16, fp32 accum.
// R8: register double-buffered ldsm fragments; STOREB hoisted before MMA
//     (one-iteration-deeper software pipeline) to shrink live ranges.

#define BM 128
#define BN 128
#define BK 64
#define NTH 128
#define ROWB 144                      // 16B-aligned; (9r+c)%8 = (r+c)%8 -> ldsm conflict-free
#define A_BYTES (128 * ROWB)          // 18432
#define B_OFF   A_BYTES
#define STAGE_BYTES (2 * A_BYTES)     // 36864
#define SMEM_BYTES (2 * STAGE_BYTES)  // 73728

#define MCAP 4096
#define KCAP 8192
__device__ __half g_xh[(size_t)MCAP * KCAP];   // pre-converted x (fp16)

__device__ __forceinline__ uint32_t smem_u32(const void* p) {
    uint32_t a;
    asm("{ .reg .u64 t; cvta.to.shared.u64 t, %1; cvt.u32.u64 %0, t; }" : "=r"(a) : "l"(p));
    return a;
}
__device__ __forceinline__ void ldsm4(uint32_t r[4], uint32_t addr) {
    asm volatile("ldmatrix.sync.aligned.m8n8.x4.shared.b16 {%0,%1,%2,%3}, [%4];"
                 : "=r"(r[0]), "=r"(r[1]), "=r"(r[2]), "=r"(r[3]) : "r"(addr));
}
__device__ __forceinline__ void mma16816(float c[4], const uint32_t a[4],
                                         uint32_t b0, uint32_t b1) {
    asm volatile("mma.sync.aligned.m16n8k16.row.col.f32.f16.f16.f32 "
                 "{%0,%1,%2,%3}, {%4,%5,%6,%7}, {%8,%9}, {%0,%1,%2,%3};"
                 : "+f"(c[0]), "+f"(c[1]), "+f"(c[2]), "+f"(c[3])
                 : "r"(a[0]), "r"(a[1]), "r"(a[2]), "r"(a[3]), "r"(b0), "r"(b1));
}
__device__ __forceinline__ void sts64(uint32_t addr, uint32_t a, uint32_t b) {
    asm volatile("st.shared.v2.b32 [%0], {%1,%2};" :: "r"(addr), "r"(a), "r"(b));
}
__device__ __forceinline__ uint32_t h2u(__half2 h) { return *reinterpret_cast<uint32_t*>(&h); }
__device__ __forceinline__ __half2 u2h(uint32_t u) { return *reinterpret_cast<__half2*>(&u); }

// ---- pre-pass: fp32 x -> fp16 g_xh ----
__global__ void cvt_kernel(const float* __restrict__ x, size_t n4) {
    size_t i = (size_t)blockIdx.x * blockDim.x + threadIdx.x;
    const size_t stride = (size_t)gridDim.x * blockDim.x;
    for (; i < n4; i += stride) {
        float4 v = ((const float4*)x)[i];
        __half2 h0 = __floats2half2_rn(v.x, v.y);
        __half2 h1 = __floats2half2_rn(v.z, v.w);
        uint2 u; u.x = h2u(h0); u.y = h2u(h1);
        ((uint2*)g_xh)[i] = u;
    }
}

__global__ __launch_bounds__(NTH, 2)
void q4_hmma_kernel(const int*   __restrict__ qw,
                    const float* __restrict__ scales,
                    const float* __restrict__ bias,
                    float* __restrict__ out,
                    int M, int N, int K, int NB)
{
    extern __shared__ __align__(128) char smem[];
    const uint32_t sbase = smem_u32(smem);

    const int tid  = threadIdx.x;
    const int lane = tid & 31;
    const int wid  = tid >> 5;
    const int bm   = blockIdx.y * BM;
    const int bn   = blockIdx.x * BN;
    const int NT   = K / BK;   // 128

    // 4 warps: 2 (m) x 2 (n), warp tile 64x64
    const int m_off = (wid & 1) * 64;
    const int n_off = (wid >> 1) * 64;

    const uint32_t aLd = (uint32_t)((m_off + (lane & 15)) * ROWB + (lane >> 4) * 16);
    const uint32_t bLd = (uint32_t)((n_off + (lane & 7) + ((lane & 16) ? 8 : 0)) * ROWB
                                    + ((lane >> 3) & 1) * 16);

    float acc[4][8][4];
    #pragma unroll
    for (int i = 0; i < 4; ++i)
        #pragma unroll
        for (int j = 0; j < 8; ++j)
            #pragma unroll
            for (int v = 0; v < 4; ++v) acc[i][j][v] = 0.0f;

    const uint32_t c1032 = 0x64086408u;    // half2(1032,1032)
    int4  bv[8];
    float sc[8];

#define CPA(KT)                                                                        \
    do {                                                                               \
        const uint32_t st = sbase + ((KT) & 1) * STAGE_BYTES;                          \
        const __half* gA = &g_xh[(size_t)bm * K + (size_t)(KT) * BK];                  \
        _Pragma("unroll")                                                              \
        for (int i = 0; i < 8; ++i) {                                                  \
            int idx = tid + i * NTH, row = idx >> 3, c = idx & 7;                      \
            uint32_t d = st + (uint32_t)(row * ROWB + c * 16);                         \
            const void* s = gA + (size_t)row * K + c * 8;                              \
            asm volatile("cp.async.cg.shared.global [%0], [%1], 16;"                   \
                         :: "r"(d), "l"(s));                                           \
        }                                                                              \
        asm volatile("cp.async.commit_group;");                                        \
    } while (0)

#define LOADB(KT)                                                                      \
    do {                                                                               \
        _Pragma("unroll")                                                              \
        for (int i = 0; i < 8; ++i) {                                                  \
            int idx = tid + i * NTH, row = idx >> 3, t8 = idx & 7;                     \
            const int* qb = qw + ((size_t)(bn + row) * NB + (KT) * 2) * 16 + t8 * 4;   \
            bv[i] = *(const int4*)qb;                                                  \
            sc[i] = __ldg(&scales[(size_t)(bn + row) * NB + (KT) * 2 + (t8 >> 2)]);    \
        }                                                                              \
    } while (0)

#define STOREB(KT)                                                                     \
    do {                                                                               \
        const uint32_t st = sbase + ((KT) & 1) * STAGE_BYTES;                          \
        _Pragma("unroll")                                                              \
        for (int i = 0; i < 8; ++i) {                                                  \
            int idx = tid + i * NTH, row = idx >> 3, t8 = idx & 7;                     \
            int blk = t8 >> 2, c = t8 & 3;                                             \
            __half2 s2 = __half2half2(__float2half_rn(sc[i]));                         \
            int q0 = bv[i].x, q1 = bv[i].y, q2 = bv[i].z, q3 = bv[i].w;                \
            uint32_t lo0 = (uint32_t)(q0 & 0xF) | (((uint32_t)(q1 & 0xF)) << 16)       \
                           | 0x64006400u;                                              \
            uint32_t lo1 = (uint32_t)(q2 & 0xF) | (((uint32_t)(q3 & 0xF)) << 16)       \
                           | 0x64006400u;                                              \
            uint32_t hi0 = (uint32_t)((q0 >> 4) & 0xF)                                 \
                           | (((uint32_t)((q1 >> 4) & 0xF)) << 16) | 0x64006400u;      \
            uint32_t hi1 = (uint32_t)((q2 >> 4) & 0xF)                                 \
                           | (((uint32_t)((q3 >> 4) & 0xF)) << 16) | 0x64006400u;      \
            uint32_t wl0 = h2u(__hmul2(__hsub2(u2h(lo0), u2h(c1032)), s2));            \
            uint32_t wl1 = h2u(__hmul2(__hsub2(u2h(lo1), u2h(c1032)), s2));            \
            uint32_t wh0 = h2u(__hmul2(__hsub2(u2h(hi0), u2h(c1032)), s2));            \
            uint32_t wh1 = h2u(__hmul2(__hsub2(u2h(hi1), u2h(c1032)), s2));            \
            uint32_t dst = st + B_OFF + (uint32_t)(row * ROWB + blk * 64 + c * 8);     \
            sts64(dst,      wl0, wl1);                                                 \
            sts64(dst + 32, wh0, wh1);                                                 \
        }                                                                              \
    } while (0)

#define LDFRAG(BUF, KS)                                                                \
    do {                                                                               \
        _Pragma("unroll")                                                              \
        for (int mf = 0; mf < 4; ++mf)                                                 \
            ldsm4(afr[BUF][mf], aB + (uint32_t)(mf * 16 * ROWB + (KS) * 32));          \
        _Pragma("unroll")                                                              \
        for (int np = 0; np < 4; ++np)                                                 \
            ldsm4(bfr[BUF][np], bB + (uint32_t)(np * 16 * ROWB + (KS) * 32));          \
    } while (0)

#define DOMMA(BUF)                                                                     \
    do {                                                                               \
        _Pragma("unroll")                                                              \
        for (int mf = 0; mf < 4; ++mf)                                                 \
            _Pragma("unroll")                                                          \
            for (int nf = 0; nf < 8; ++nf)                                             \
                mma16816(acc[mf][nf], afr[BUF][mf],                                    \
                         bfr[BUF][nf >> 1][(nf & 1) * 2],                              \
                         bfr[BUF][nf >> 1][(nf & 1) * 2 + 1]);                         \
    } while (0)

    // prologue: fill stage 0; prefetch B data for tile 1
    LOADB(0);
    STOREB(0);
    CPA(0);
    LOADB(1);

    for (int kt = 0; kt < NT; ++kt) {
        const int kn = kt + 1;

        // stage kt's cp.async must have landed; barrier publishes STS of stage kt
        asm volatile("cp.async.wait_group 0;" ::: "memory");
        __syncthreads();

        if (kn < NT) {
            CPA(kn);        // A stage kn&1 (MMA(kt-1) on it finished before barrier)
            STOREB(kn);     // B stage kn&1, from data LDG'd one iteration ago
            if (kn + 1 < NT) LOADB(kn + 1);   // LDG latency hides under MMA(kt)
        }

        // ---- MMA on stage kt, register double-buffered fragments ----
        {
            const uint32_t st = sbase + (kt & 1) * STAGE_BYTES;
            const uint32_t aB = st + aLd;
            const uint32_t bB = st + B_OFF + bLd;
            uint32_t afr[2][4][4], bfr[2][4][4];
            LDFRAG(0, 0);
            #pragma unroll
            for (int ks = 0; ks < 4; ++ks) {
                if (ks < 3) LDFRAG((ks + 1) & 1, ks + 1);
                DOMMA(ks & 1);
            }
        }
    }

    // ---- epilogue: bias + store ----
    {
        const int g = lane >> 2, t = lane & 3;
        #pragma unroll
        for (int nf = 0; nf < 8; ++nf) {
            const int col = bn + n_off + nf * 8 + 2 * t;
            const float2 bb = *(const float2*)&bias[col];
            #pragma unroll
            for (int mf = 0; mf < 4; ++mf) {
                const int row = bm + m_off + mf * 16 + g;
                float2 o0, o1;
                o0.x = acc[mf][nf][0] + bb.x;
                o0.y = acc[mf][nf][1] + bb.y;
                o1.x = acc[mf][nf][2] + bb.x;
                o1.y = acc[mf][nf][3] + bb.y;
                *(float2*)&out[(size_t)row * N + col]       = o0;
                *(float2*)&out[(size_t)(row + 8) * N + col] = o1;
            }
        }
    }
}

extern "C" void kernel_launch(void* const* d_in, const int* in_sizes, int n_in,
                              void* d_out, int out_size)
{
    const float* x      = (const float*)d_in[0];
    const int*   qw     = (const int*)  d_in[1];
    const float* scales = (const float*)d_in[2];
    const float* bias   = (const float*)d_in[3];
    float*       out    = (float*)d_out;

    const int O  = in_sizes[3];            // 8192
    const int NB = in_sizes[2] / O;        // 256
    const int K  = NB * 32;                // 8192
    const int M  = in_sizes[0] / K;        // 4096
    const int N  = O;

    // pre-pass: x -> fp16
    cvt_kernel<<<1024, 256>>>(x, (size_t)M * K / 4);

    cudaFuncSetAttribute(q4_hmma_kernel, cudaFuncAttributeMaxDynamicSharedMemorySize,
                         SMEM_BYTES);
    dim3 grid(N / BN, M / BM);
    q4_hmma_kernel<<<grid, NTH, SMEM_BYTES>>>(qw, scales, bias, out, M, N, K, NB);
}

// round 9
// speedup vs baseline: 1.4873x; 1.4873x over previous
#include <cuda_runtime.h>
#include <cuda_fp16.h>
#include <cstdint>

// Q4_0 dequant GEMM via mma.sync (HMMA) fp16, fp32 accum.
// R9: R7 structure + 3-stage smem pipeline. Producers fill stage kt+2 while
//     MMA consumes stage kt -> STS is 2 barriers ahead of its ldsm.
//     (R8's register fragment double-buffer reverted: it spilled.)

#define BM 128
#define BN 128
#define BK 64
#define NTH 128
#define ROWB 144                      // 16B-aligned; (9r+c)%8 = (r+c)%8 -> ldsm conflict-free
#define A_BYTES (128 * ROWB)          // 18432
#define B_OFF   A_BYTES
#define STAGE_BYTES (2 * A_BYTES)     // 36864
#define NSTAGE 3
#define SMEM_BYTES (NSTAGE * STAGE_BYTES)  // 110592

#define MCAP 4096
#define KCAP 8192
__device__ __half g_xh[(size_t)MCAP * KCAP];   // pre-converted x (fp16)

__device__ __forceinline__ uint32_t smem_u32(const void* p) {
    uint32_t a;
    asm("{ .reg .u64 t; cvta.to.shared.u64 t, %1; cvt.u32.u64 %0, t; }" : "=r"(a) : "l"(p));
    return a;
}
__device__ __forceinline__ void ldsm4(uint32_t r[4], uint32_t addr) {
    asm volatile("ldmatrix.sync.aligned.m8n8.x4.shared.b16 {%0,%1,%2,%3}, [%4];"
                 : "=r"(r[0]), "=r"(r[1]), "=r"(r[2]), "=r"(r[3]) : "r"(addr));
}
__device__ __forceinline__ void mma16816(float c[4], const uint32_t a[4],
                                         uint32_t b0, uint32_t b1) {
    asm volatile("mma.sync.aligned.m16n8k16.row.col.f32.f16.f16.f32 "
                 "{%0,%1,%2,%3}, {%4,%5,%6,%7}, {%8,%9}, {%0,%1,%2,%3};"
                 : "+f"(c[0]), "+f"(c[1]), "+f"(c[2]), "+f"(c[3])
                 : "r"(a[0]), "r"(a[1]), "r"(a[2]), "r"(a[3]), "r"(b0), "r"(b1));
}
__device__ __forceinline__ void sts64(uint32_t addr, uint32_t a, uint32_t b) {
    asm volatile("st.shared.v2.b32 [%0], {%1,%2};" :: "r"(addr), "r"(a), "r"(b));
}
__device__ __forceinline__ uint32_t h2u(__half2 h) { return *reinterpret_cast<uint32_t*>(&h); }
__device__ __forceinline__ __half2 u2h(uint32_t u) { return *reinterpret_cast<__half2*>(&u); }

// ---- pre-pass: fp32 x -> fp16 g_xh ----
__global__ void cvt_kernel(const float* __restrict__ x, size_t n4) {
    size_t i = (size_t)blockIdx.x * blockDim.x + threadIdx.x;
    const size_t stride = (size_t)gridDim.x * blockDim.x;
    for (; i < n4; i += stride) {
        float4 v = ((const float4*)x)[i];
        __half2 h0 = __floats2half2_rn(v.x, v.y);
        __half2 h1 = __floats2half2_rn(v.z, v.w);
        uint2 u; u.x = h2u(h0); u.y = h2u(h1);
        ((uint2*)g_xh)[i] = u;
    }
}

__global__ __launch_bounds__(NTH, 2)
void q4_hmma_kernel(const int*   __restrict__ qw,
                    const float* __restrict__ scales,
                    const float* __restrict__ bias,
                    float* __restrict__ out,
                    int M, int N, int K, int NB)
{
    extern __shared__ __align__(128) char smem[];
    const uint32_t sbase = smem_u32(smem);

    const int tid  = threadIdx.x;
    const int lane = tid & 31;
    const int wid  = tid >> 5;
    const int bm   = blockIdx.y * BM;
    const int bn   = blockIdx.x * BN;
    const int NT   = K / BK;   // 128

    // 4 warps: 2 (m) x 2 (n), warp tile 64x64
    const int m_off = (wid & 1) * 64;
    const int n_off = (wid >> 1) * 64;

    const uint32_t aLd = (uint32_t)((m_off + (lane & 15)) * ROWB + (lane >> 4) * 16);
    const uint32_t bLd = (uint32_t)((n_off + (lane & 7) + ((lane & 16) ? 8 : 0)) * ROWB
                                    + ((lane >> 3) & 1) * 16);

    float acc[4][8][4];
    #pragma unroll
    for (int i = 0; i < 4; ++i)
        #pragma unroll
        for (int j = 0; j < 8; ++j)
            #pragma unroll
            for (int v = 0; v < 4; ++v) acc[i][j][v] = 0.0f;

    const uint32_t c1032 = 0x64086408u;    // half2(1032,1032)
    int4  bv[8];
    float sc[8];

#define CPA(KT)                                                                        \
    do {                                                                               \
        const uint32_t st = sbase + ((KT) % NSTAGE) * STAGE_BYTES;                     \
        const __half* gA = &g_xh[(size_t)bm * K + (size_t)(KT) * BK];                  \
        _Pragma("unroll")                                                              \
        for (int i = 0; i < 8; ++i) {                                                  \
            int idx = tid + i * NTH, row = idx >> 3, c = idx & 7;                      \
            uint32_t d = st + (uint32_t)(row * ROWB + c * 16);                         \
            const void* s = gA + (size_t)row * K + c * 8;                              \
            asm volatile("cp.async.cg.shared.global [%0], [%1], 16;"                   \
                         :: "r"(d), "l"(s));                                           \
        }                                                                              \
        asm volatile("cp.async.commit_group;");                                        \
    } while (0)

#define LOADB(KT)                                                                      \
    do {                                                                               \
        _Pragma("unroll")                                                              \
        for (int i = 0; i < 8; ++i) {                                                  \
            int idx = tid + i * NTH, row = idx >> 3, t8 = idx & 7;                     \
            const int* qb = qw + ((size_t)(bn + row) * NB + (KT) * 2) * 16 + t8 * 4;   \
            bv[i] = *(const int4*)qb;                                                  \
            sc[i] = __ldg(&scales[(size_t)(bn + row) * NB + (KT) * 2 + (t8 >> 2)]);    \
        }                                                                              \
    } while (0)

#define STOREB(KT)                                                                     \
    do {                                                                               \
        const uint32_t st = sbase + ((KT) % NSTAGE) * STAGE_BYTES;                     \
        _Pragma("unroll")                                                              \
        for (int i = 0; i < 8; ++i) {                                                  \
            int idx = tid + i * NTH, row = idx >> 3, t8 = idx & 7;                     \
            int blk = t8 >> 2, c = t8 & 3;                                             \
            __half2 s2 = __half2half2(__float2half_rn(sc[i]));                         \
            int q0 = bv[i].x, q1 = bv[i].y, q2 = bv[i].z, q3 = bv[i].w;                \
            uint32_t lo0 = (uint32_t)(q0 & 0xF) | (((uint32_t)(q1 & 0xF)) << 16)       \
                           | 0x64006400u;                                              \
            uint32_t lo1 = (uint32_t)(q2 & 0xF) | (((uint32_t)(q3 & 0xF)) << 16)       \
                           | 0x64006400u;                                              \
            uint32_t hi0 = (uint32_t)((q0 >> 4) & 0xF)                                 \
                           | (((uint32_t)((q1 >> 4) & 0xF)) << 16) | 0x64006400u;      \
            uint32_t hi1 = (uint32_t)((q2 >> 4) & 0xF)                                 \
                           | (((uint32_t)((q3 >> 4) & 0xF)) << 16) | 0x64006400u;      \
            uint32_t wl0 = h2u(__hmul2(__hsub2(u2h(lo0), u2h(c1032)), s2));            \
            uint32_t wl1 = h2u(__hmul2(__hsub2(u2h(lo1), u2h(c1032)), s2));            \
            uint32_t wh0 = h2u(__hmul2(__hsub2(u2h(hi0), u2h(c1032)), s2));            \
            uint32_t wh1 = h2u(__hmul2(__hsub2(u2h(hi1), u2h(c1032)), s2));            \
            uint32_t dst = st + B_OFF + (uint32_t)(row * ROWB + blk * 64 + c * 8);     \
            sts64(dst,      wl0, wl1);                                                 \
            sts64(dst + 32, wh0, wh1);                                                 \
        }                                                                              \
    } while (0)

    // prologue: fill stages 0 and 1; prefetch B data for tile 2
    LOADB(0); STOREB(0); CPA(0);
    LOADB(1); STOREB(1); CPA(1);
    LOADB(2);

    for (int kt = 0; kt < NT; ++kt) {
        // A of stage kt landed (committed >= 2 groups ago except final tile)
        if (kt + 1 < NT) {
            asm volatile("cp.async.wait_group 1;" ::: "memory");
        } else {
            asm volatile("cp.async.wait_group 0;" ::: "memory");
        }
        __syncthreads();   // all warps finished MMA(kt-1) -> stage (kt+2)%3 reusable

        const int k2 = kt + 2, k3 = kt + 3;
        if (k2 < NT) {
            CPA(k2);
            STOREB(k2);            // from bv loaded last iteration
        }
        if (k3 < NT) LOADB(k3);    // LDG latency hides under MMA(kt)

        // ---- MMA on stage kt ----
        {
            const uint32_t st = sbase + (kt % NSTAGE) * STAGE_BYTES;
            const uint32_t aB = st + aLd;
            const uint32_t bB = st + B_OFF + bLd;
            #pragma unroll
            for (int ks = 0; ks < 4; ++ks) {
                uint32_t a[4][4];
                #pragma unroll
                for (int mf = 0; mf < 4; ++mf)
                    ldsm4(a[mf], aB + (uint32_t)(mf * 16 * ROWB + ks * 32));
                uint32_t b[4][4];
                #pragma unroll
                for (int np = 0; np < 4; ++np)
                    ldsm4(b[np], bB + (uint32_t)(np * 16 * ROWB + ks * 32));
                #pragma unroll
                for (int mf = 0; mf < 4; ++mf)
                    #pragma unroll
                    for (int nf = 0; nf < 8; ++nf)
                        mma16816(acc[mf][nf], a[mf], b[nf >> 1][(nf & 1) * 2],
                                 b[nf >> 1][(nf & 1) * 2 + 1]);
            }
        }
    }

    // ---- epilogue: bias + store ----
    {
        const int g = lane >> 2, t = lane & 3;
        #pragma unroll
        for (int nf = 0; nf < 8; ++nf) {
            const int col = bn + n_off + nf * 8 + 2 * t;
            const float2 bb = *(const float2*)&bias[col];
            #pragma unroll
            for (int mf = 0; mf < 4; ++mf) {
                const int row = bm + m_off + mf * 16 + g;
                float2 o0, o1;
                o0.x = acc[mf][nf][0] + bb.x;
                o0.y = acc[mf][nf][1] + bb.y;
                o1.x = acc[mf][nf][2] + bb.x;
                o1.y = acc[mf][nf][3] + bb.y;
                *(float2*)&out[(size_t)row * N + col]       = o0;
                *(float2*)&out[(size_t)(row + 8) * N + col] = o1;
            }
        }
    }
}

extern "C" void kernel_launch(void* const* d_in, const int* in_sizes, int n_in,
                              void* d_out, int out_size)
{
    const float* x      = (const float*)d_in[0];
    const int*   qw     = (const int*)  d_in[1];
    const float* scales = (const float*)d_in[2];
    const float* bias   = (const float*)d_in[3];
    float*       out    = (float*)d_out;

    const int O  = in_sizes[3];            // 8192
    const int NB = in_sizes[2] / O;        // 256
    const int K  = NB * 32;                // 8192
    const int M  = in_sizes[0] / K;        // 4096
    const int N  = O;

    // pre-pass: x -> fp16
    cvt_kernel<<<1024, 256>>>(x, (size_t)M * K / 4);

    cudaFuncSetAttribute(q4_hmma_kernel, cudaFuncAttributeMaxDynamicSharedMemorySize,
                         SMEM_BYTES);
    dim3 grid(N / BN, M / BM);
    q4_hmma_kernel<<<grid, NTH, SMEM_BYTES>>>(qw, scales, bias, out, M, N, K, NB);
}

// round 10
// speedup vs baseline: 1.6969x; 1.1409x over previous
#include <cuda_runtime.h>
#include <cuda_fp16.h>
#include <cstdint>

// Q4_0 dequant GEMM, R10: W pre-dequantized to fp16 in a pre-pass (same gmem
// bytes: 16 byte-valued int32 = 64B = 32 fp16). Main kernel = clean fp16 HMMA
// GEMM, both operands via cp.async, 3-stage ring, no in-loop dequant.

#define BM 128
#define BN 128
#define BK 64
#define NTH 128
#define ROWB 144                      // 16B-aligned; (9r+c)%8 = (r+c)%8 -> ldsm conflict-free
#define A_BYTES (128 * ROWB)          // 18432
#define B_OFF   A_BYTES
#define STAGE_BYTES (2 * A_BYTES)     // 36864
#define NSTAGE 3
#define SMEM_BYTES (NSTAGE * STAGE_BYTES)  // 110592

#define MCAP 4096
#define KCAP 8192
#define OCAP 8192
__device__ __half g_xh[(size_t)MCAP * KCAP];   // x  -> fp16
__device__ __half g_wh[(size_t)OCAP * KCAP];   // W  -> fp16 (dequantized)

__device__ __forceinline__ uint32_t smem_u32(const void* p) {
    uint32_t a;
    asm("{ .reg .u64 t; cvta.to.shared.u64 t, %1; cvt.u32.u64 %0, t; }" : "=r"(a) : "l"(p));
    return a;
}
__device__ __forceinline__ void ldsm4(uint32_t r[4], uint32_t addr) {
    asm volatile("ldmatrix.sync.aligned.m8n8.x4.shared.b16 {%0,%1,%2,%3}, [%4];"
                 : "=r"(r[0]), "=r"(r[1]), "=r"(r[2]), "=r"(r[3]) : "r"(addr));
}
__device__ __forceinline__ void mma16816(float c[4], const uint32_t a[4],
                                         uint32_t b0, uint32_t b1) {
    asm volatile("mma.sync.aligned.m16n8k16.row.col.f32.f16.f16.f32 "
                 "{%0,%1,%2,%3}, {%4,%5,%6,%7}, {%8,%9}, {%0,%1,%2,%3};"
                 : "+f"(c[0]), "+f"(c[1]), "+f"(c[2]), "+f"(c[3])
                 : "r"(a[0]), "r"(a[1]), "r"(a[2]), "r"(a[3]), "r"(b0), "r"(b1));
}
__device__ __forceinline__ uint32_t h2u(__half2 h) { return *reinterpret_cast<uint32_t*>(&h); }
__device__ __forceinline__ __half2 u2h(uint32_t u) { return *reinterpret_cast<__half2*>(&u); }

// ---- pre-pass 1: fp32 x -> fp16 ----
__global__ void cvt_kernel(const float* __restrict__ x, size_t n4) {
    size_t i = (size_t)blockIdx.x * blockDim.x + threadIdx.x;
    const size_t stride = (size_t)gridDim.x * blockDim.x;
    for (; i < n4; i += stride) {
        float4 v = ((const float4*)x)[i];
        __half2 h0 = __floats2half2_rn(v.x, v.y);
        __half2 h1 = __floats2half2_rn(v.z, v.w);
        uint2 u; u.x = h2u(h0); u.y = h2u(h1);
        ((uint2*)g_xh)[i] = u;
    }
}

// ---- pre-pass 2: Q4_0 -> fp16 W. One thread per 32-weight block. ----
// Block b (= o*NB + nb) reads 16 byte-valued int32 + 1 scale, writes 32 fp16
// contiguously at g_wh + b*32 (since row-major [O, K] and 32 = BLOCK).
__global__ void dq_kernel(const int* __restrict__ qw,
                          const float* __restrict__ scales, size_t nblk) {
    const uint32_t c1032 = 0x64086408u;    // half2(1032,1032); nib+1024-1032 = nib-8 exact
    size_t b = (size_t)blockIdx.x * blockDim.x + threadIdx.x;
    const size_t stride = (size_t)gridDim.x * blockDim.x;
    for (; b < nblk; b += stride) {
        const int4* qp = (const int4*)(qw + b * 16);
        int4 v0 = qp[0], v1 = qp[1], v2 = qp[2], v3 = qp[3];
        int q[16] = {v0.x, v0.y, v0.z, v0.w, v1.x, v1.y, v1.z, v1.w,
                     v2.x, v2.y, v2.z, v2.w, v3.x, v3.y, v3.z, v3.w};
        __half2 s2 = __half2half2(__float2half_rn(scales[b]));
        uint32_t w[16];
        #pragma unroll
        for (int j = 0; j < 8; ++j) {
            int q0 = q[2 * j], q1 = q[2 * j + 1];
            uint32_t lo = (uint32_t)(q0 & 0xF) | (((uint32_t)(q1 & 0xF)) << 16) | 0x64006400u;
            uint32_t hi = (uint32_t)((q0 >> 4) & 0xF)
                          | (((uint32_t)((q1 >> 4) & 0xF)) << 16) | 0x64006400u;
            w[j]     = h2u(__hmul2(__hsub2(u2h(lo), u2h(c1032)), s2));
            w[8 + j] = h2u(__hmul2(__hsub2(u2h(hi), u2h(c1032)), s2));
        }
        uint4* op = (uint4*)(g_wh + b * 32);
        op[0] = make_uint4(w[0],  w[1],  w[2],  w[3]);
        op[1] = make_uint4(w[4],  w[5],  w[6],  w[7]);
        op[2] = make_uint4(w[8],  w[9],  w[10], w[11]);
        op[3] = make_uint4(w[12], w[13], w[14], w[15]);
    }
}

__global__ __launch_bounds__(NTH, 2)
void q4_hmma_kernel(const float* __restrict__ bias,
                    float* __restrict__ out,
                    int M, int N, int K)
{
    extern __shared__ __align__(128) char smem[];
    const uint32_t sbase = smem_u32(smem);

    const int tid  = threadIdx.x;
    const int lane = tid & 31;
    const int wid  = tid >> 5;
    const int bm   = blockIdx.y * BM;
    const int bn   = blockIdx.x * BN;
    const int NT   = K / BK;   // 128

    // 4 warps: 2 (m) x 2 (n), warp tile 64x64
    const int m_off = (wid & 1) * 64;
    const int n_off = (wid >> 1) * 64;

    const uint32_t aLd = (uint32_t)((m_off + (lane & 15)) * ROWB + (lane >> 4) * 16);
    const uint32_t bLd = (uint32_t)((n_off + (lane & 7) + ((lane & 16) ? 8 : 0)) * ROWB
                                    + ((lane >> 3) & 1) * 16);

    float acc[4][8][4];
    #pragma unroll
    for (int i = 0; i < 4; ++i)
        #pragma unroll
        for (int j = 0; j < 8; ++j)
            #pragma unroll
            for (int v = 0; v < 4; ++v) acc[i][j][v] = 0.0f;

    // per-thread cp.async coordinates: row = tid>>3 + 16*i ... pattern idx = tid + i*NTH
    // A tile: 128 rows x 128B; B tile: 128 rows x 128B. 8 ops each, 16B per op.
#define CPAB(KT)                                                                       \
    do {                                                                               \
        const uint32_t st = sbase + ((KT) % NSTAGE) * STAGE_BYTES;                     \
        const __half* gA = &g_xh[(size_t)bm * K + (size_t)(KT) * BK];                  \
        const __half* gB = &g_wh[(size_t)bn * K + (size_t)(KT) * BK];                  \
        _Pragma("unroll")                                                              \
        for (int i = 0; i < 8; ++i) {                                                  \
            int idx = tid + i * NTH, row = idx >> 3, c = idx & 7;                      \
            uint32_t d = st + (uint32_t)(row * ROWB + c * 16);                         \
            const void* s = gA + (size_t)row * K + c * 8;                              \
            asm volatile("cp.async.cg.shared.global [%0], [%1], 16;" :: "r"(d), "l"(s)); \
        }                                                                              \
        _Pragma("unroll")                                                              \
        for (int i = 0; i < 8; ++i) {                                                  \
            int idx = tid + i * NTH, row = idx >> 3, c = idx & 7;                      \
            uint32_t d = st + B_OFF + (uint32_t)(row * ROWB + c * 16);                 \
            const void* s = gB + (size_t)row * K + c * 8;                              \
            asm volatile("cp.async.cg.shared.global [%0], [%1], 16;" :: "r"(d), "l"(s)); \
        }                                                                              \
        asm volatile("cp.async.commit_group;");                                        \
    } while (0)

    // prologue: stages 0, 1
    CPAB(0);
    CPAB(1);

    for (int kt = 0; kt < NT; ++kt) {
        if (kt + 1 < NT) {
            asm volatile("cp.async.wait_group 1;" ::: "memory");
        } else {
            asm volatile("cp.async.wait_group 0;" ::: "memory");
        }
        __syncthreads();   // all warps done with MMA(kt-1) -> stage (kt+2)%3 free

        const int k2 = kt + 2;
        if (k2 < NT) CPAB(k2);

        // ---- MMA on stage kt ----
        {
            const uint32_t st = sbase + (kt % NSTAGE) * STAGE_BYTES;
            const uint32_t aB = st + aLd;
            const uint32_t bB = st + B_OFF + bLd;
            #pragma unroll
            for (int ks = 0; ks < 4; ++ks) {
                uint32_t a[4][4];
                #pragma unroll
                for (int mf = 0; mf < 4; ++mf)
                    ldsm4(a[mf], aB + (uint32_t)(mf * 16 * ROWB + ks * 32));
                uint32_t b[4][4];
                #pragma unroll
                for (int np = 0; np < 4; ++np)
                    ldsm4(b[np], bB + (uint32_t)(np * 16 * ROWB + ks * 32));
                #pragma unroll
                for (int mf = 0; mf < 4; ++mf)
                    #pragma unroll
                    for (int nf = 0; nf < 8; ++nf)
                        mma16816(acc[mf][nf], a[mf], b[nf >> 1][(nf & 1) * 2],
                                 b[nf >> 1][(nf & 1) * 2 + 1]);
            }
        }
    }

    // ---- epilogue: bias + store ----
    {
        const int g = lane >> 2, t = lane & 3;
        #pragma unroll
        for (int nf = 0; nf < 8; ++nf) {
            const int col = bn + n_off + nf * 8 + 2 * t;
            const float2 bb = *(const float2*)&bias[col];
            #pragma unroll
            for (int mf = 0; mf < 4; ++mf) {
                const int row = bm + m_off + mf * 16 + g;
                float2 o0, o1;
                o0.x = acc[mf][nf][0] + bb.x;
                o0.y = acc[mf][nf][1] + bb.y;
                o1.x = acc[mf][nf][2] + bb.x;
                o1.y = acc[mf][nf][3] + bb.y;
                *(float2*)&out[(size_t)row * N + col]       = o0;
                *(float2*)&out[(size_t)(row + 8) * N + col] = o1;
            }
        }
    }
}

extern "C" void kernel_launch(void* const* d_in, const int* in_sizes, int n_in,
                              void* d_out, int out_size)
{
    const float* x      = (const float*)d_in[0];
    const int*   qw     = (const int*)  d_in[1];
    const float* scales = (const float*)d_in[2];
    const float* bias   = (const float*)d_in[3];
    float*       out    = (float*)d_out;

    const int O  = in_sizes[3];            // 8192
    const int NB = in_sizes[2] / O;        // 256
    const int K  = NB * 32;                // 8192
    const int M  = in_sizes[0] / K;        // 4096
    const int N  = O;

    // pre-passes: x -> fp16, W -> fp16
    cvt_kernel<<<1024, 256>>>(x, (size_t)M * K / 4);
    dq_kernel<<<2048, 256>>>(qw, scales, (size_t)O * NB);

    cudaFuncSetAttribute(q4_hmma_kernel, cudaFuncAttributeMaxDynamicSharedMemorySize,
                         SMEM_BYTES);
    dim3 grid(N / BN, M / BM);
    q4_hmma_kernel<<<grid, NTH, SMEM_BYTES>>>(bias, out, M, N, K);
}

// round 11
// speedup vs baseline: 1.7047x; 1.0046x over previous
#include <cuda_runtime.h>
#include <cuda_fp16.h>
#include <cstdint>

// Q4_0 dequant GEMM, R11: R10 (pre-dequantized fp16 W + clean HMMA GEMM)
// + register double-buffered ldsm fragments (retry of R8's idea, now viable
// because producer machinery is gone and regs have headroom).

#define BM 128
#define BN 128
#define BK 64
#define NTH 128
#define ROWB 144                      // 16B-aligned; (9r+c)%8 = (r+c)%8 -> ldsm conflict-free
#define A_BYTES (128 * ROWB)          // 18432
#define B_OFF   A_BYTES
#define STAGE_BYTES (2 * A_BYTES)     // 36864
#define NSTAGE 3
#define SMEM_BYTES (NSTAGE * STAGE_BYTES)  // 110592

#define MCAP 4096
#define KCAP 8192
#define OCAP 8192
__device__ __half g_xh[(size_t)MCAP * KCAP];   // x  -> fp16
__device__ __half g_wh[(size_t)OCAP * KCAP];   // W  -> fp16 (dequantized)

__device__ __forceinline__ uint32_t smem_u32(const void* p) {
    uint32_t a;
    asm("{ .reg .u64 t; cvta.to.shared.u64 t, %1; cvt.u32.u64 %0, t; }" : "=r"(a) : "l"(p));
    return a;
}
__device__ __forceinline__ void ldsm4(uint32_t r[4], uint32_t addr) {
    asm volatile("ldmatrix.sync.aligned.m8n8.x4.shared.b16 {%0,%1,%2,%3}, [%4];"
                 : "=r"(r[0]), "=r"(r[1]), "=r"(r[2]), "=r"(r[3]) : "r"(addr));
}
__device__ __forceinline__ void mma16816(float c[4], const uint32_t a[4],
                                         uint32_t b0, uint32_t b1) {
    asm volatile("mma.sync.aligned.m16n8k16.row.col.f32.f16.f16.f32 "
                 "{%0,%1,%2,%3}, {%4,%5,%6,%7}, {%8,%9}, {%0,%1,%2,%3};"
                 : "+f"(c[0]), "+f"(c[1]), "+f"(c[2]), "+f"(c[3])
                 : "r"(a[0]), "r"(a[1]), "r"(a[2]), "r"(a[3]), "r"(b0), "r"(b1));
}
__device__ __forceinline__ uint32_t h2u(__half2 h) { return *reinterpret_cast<uint32_t*>(&h); }
__device__ __forceinline__ __half2 u2h(uint32_t u) { return *reinterpret_cast<__half2*>(&u); }

// ---- pre-pass 1: fp32 x -> fp16 ----
__global__ void cvt_kernel(const float* __restrict__ x, size_t n4) {
    size_t i = (size_t)blockIdx.x * blockDim.x + threadIdx.x;
    const size_t stride = (size_t)gridDim.x * blockDim.x;
    for (; i < n4; i += stride) {
        float4 v = ((const float4*)x)[i];
        __half2 h0 = __floats2half2_rn(v.x, v.y);
        __half2 h1 = __floats2half2_rn(v.z, v.w);
        uint2 u; u.x = h2u(h0); u.y = h2u(h1);
        ((uint2*)g_xh)[i] = u;
    }
}

// ---- pre-pass 2: Q4_0 -> fp16 W. One thread per 32-weight block. ----
__global__ void dq_kernel(const int* __restrict__ qw,
                          const float* __restrict__ scales, size_t nblk) {
    const uint32_t c1032 = 0x64086408u;    // half2(1032,1032); nib+1024-1032 = nib-8 exact
    size_t b = (size_t)blockIdx.x * blockDim.x + threadIdx.x;
    const size_t stride = (size_t)gridDim.x * blockDim.x;
    for (; b < nblk; b += stride) {
        const int4* qp = (const int4*)(qw + b * 16);
        int4 v0 = qp[0], v1 = qp[1], v2 = qp[2], v3 = qp[3];
        int q[16] = {v0.x, v0.y, v0.z, v0.w, v1.x, v1.y, v1.z, v1.w,
                     v2.x, v2.y, v2.z, v2.w, v3.x, v3.y, v3.z, v3.w};
        __half2 s2 = __half2half2(__float2half_rn(scales[b]));
        uint32_t w[16];
        #pragma unroll
        for (int j = 0; j < 8; ++j) {
            int q0 = q[2 * j], q1 = q[2 * j + 1];
            uint32_t lo = (uint32_t)(q0 & 0xF) | (((uint32_t)(q1 & 0xF)) << 16) | 0x64006400u;
            uint32_t hi = (uint32_t)((q0 >> 4) & 0xF)
                          | (((uint32_t)((q1 >> 4) & 0xF)) << 16) | 0x64006400u;
            w[j]     = h2u(__hmul2(__hsub2(u2h(lo), u2h(c1032)), s2));
            w[8 + j] = h2u(__hmul2(__hsub2(u2h(hi), u2h(c1032)), s2));
        }
        uint4* op = (uint4*)(g_wh + b * 32);
        op[0] = make_uint4(w[0],  w[1],  w[2],  w[3]);
        op[1] = make_uint4(w[4],  w[5],  w[6],  w[7]);
        op[2] = make_uint4(w[8],  w[9],  w[10], w[11]);
        op[3] = make_uint4(w[12], w[13], w[14], w[15]);
    }
}

__global__ __launch_bounds__(NTH, 2)
void q4_hmma_kernel(const float* __restrict__ bias,
                    float* __restrict__ out,
                    int M, int N, int K)
{
    extern __shared__ __align__(128) char smem[];
    const uint32_t sbase = smem_u32(smem);

    const int tid  = threadIdx.x;
    const int lane = tid & 31;
    const int wid  = tid >> 5;
    const int bm   = blockIdx.y * BM;
    const int bn   = blockIdx.x * BN;
    const int NT   = K / BK;   // 128

    // 4 warps: 2 (m) x 2 (n), warp tile 64x64
    const int m_off = (wid & 1) * 64;
    const int n_off = (wid >> 1) * 64;

    const uint32_t aLd = (uint32_t)((m_off + (lane & 15)) * ROWB + (lane >> 4) * 16);
    const uint32_t bLd = (uint32_t)((n_off + (lane & 7) + ((lane & 16) ? 8 : 0)) * ROWB
                                    + ((lane >> 3) & 1) * 16);

    float acc[4][8][4];
    #pragma unroll
    for (int i = 0; i < 4; ++i)
        #pragma unroll
        for (int j = 0; j < 8; ++j)
            #pragma unroll
            for (int v = 0; v < 4; ++v) acc[i][j][v] = 0.0f;

#define CPAB(KT)                                                                       \
    do {                                                                               \
        const uint32_t st = sbase + ((KT) % NSTAGE) * STAGE_BYTES;                     \
        const __half* gA = &g_xh[(size_t)bm * K + (size_t)(KT) * BK];                  \
        const __half* gB = &g_wh[(size_t)bn * K + (size_t)(KT) * BK];                  \
        _Pragma("unroll")                                                              \
        for (int i = 0; i < 8; ++i) {                                                  \
            int idx = tid + i * NTH, row = idx >> 3, c = idx & 7;                      \
            uint32_t d = st + (uint32_t)(row * ROWB + c * 16);                         \
            const void* s = gA + (size_t)row * K + c * 8;                              \
            asm volatile("cp.async.cg.shared.global [%0], [%1], 16;" :: "r"(d), "l"(s)); \
        }                                                                              \
        _Pragma("unroll")                                                              \
        for (int i = 0; i < 8; ++i) {                                                  \
            int idx = tid + i * NTH, row = idx >> 3, c = idx & 7;                      \
            uint32_t d = st + B_OFF + (uint32_t)(row * ROWB + c * 16);                 \
            const void* s = gB + (size_t)row * K + c * 8;                              \
            asm volatile("cp.async.cg.shared.global [%0], [%1], 16;" :: "r"(d), "l"(s)); \
        }                                                                              \
        asm volatile("cp.async.commit_group;");                                        \
    } while (0)

#define LDFRAG(BUF, KS)                                                                \
    do {                                                                               \
        _Pragma("unroll")                                                              \
        for (int mf = 0; mf < 4; ++mf)                                                 \
            ldsm4(afr[BUF][mf], aB + (uint32_t)(mf * 16 * ROWB + (KS) * 32));          \
        _Pragma("unroll")                                                              \
        for (int np = 0; np < 4; ++np)                                                 \
            ldsm4(bfr[BUF][np], bB + (uint32_t)(np * 16 * ROWB + (KS) * 32));          \
    } while (0)

#define DOMMA(BUF)                                                                     \
    do {                                                                               \
        _Pragma("unroll")                                                              \
        for (int mf = 0; mf < 4; ++mf)                                                 \
            _Pragma("unroll")                                                          \
            for (int nf = 0; nf < 8; ++nf)                                             \
                mma16816(acc[mf][nf], afr[BUF][mf],                                    \
                         bfr[BUF][nf >> 1][(nf & 1) * 2],                              \
                         bfr[BUF][nf >> 1][(nf & 1) * 2 + 1]);                         \
    } while (0)

    // prologue: stages 0, 1
    CPAB(0);
    CPAB(1);

    for (int kt = 0; kt < NT; ++kt) {
        if (kt + 1 < NT) {
            asm volatile("cp.async.wait_group 1;" ::: "memory");
        } else {
            asm volatile("cp.async.wait_group 0;" ::: "memory");
        }
        __syncthreads();   // all warps done with MMA(kt-1) -> stage (kt+2)%3 free

        const int k2 = kt + 2;
        if (k2 < NT) CPAB(k2);

        // ---- MMA on stage kt, register double-buffered ldsm fragments ----
        {
            const uint32_t st = sbase + (kt % NSTAGE) * STAGE_BYTES;
            const uint32_t aB = st + aLd;
            const uint32_t bB = st + B_OFF + bLd;
            uint32_t afr[2][4][4], bfr[2][4][4];
            LDFRAG(0, 0);
            #pragma unroll
            for (int ks = 0; ks < 4; ++ks) {
                if (ks < 3) LDFRAG((ks + 1) & 1, ks + 1);
                DOMMA(ks & 1);
            }
        }
    }

    // ---- epilogue: bias + store ----
    {
        const int g = lane >> 2, t = lane & 3;
        #pragma unroll
        for (int nf = 0; nf < 8; ++nf) {
            const int col = bn + n_off + nf * 8 + 2 * t;
            const float2 bb = *(const float2*)&bias[col];
            #pragma unroll
            for (int mf = 0; mf < 4; ++mf) {
                const int row = bm + m_off + mf * 16 + g;
                float2 o0, o1;
                o0.x = acc[mf][nf][0] + bb.x;
                o0.y = acc[mf][nf][1] + bb.y;
                o1.x = acc[mf][nf][2] + bb.x;
                o1.y = acc[mf][nf][3] + bb.y;
                *(float2*)&out[(size_t)row * N + col]       = o0;
                *(float2*)&out[(size_t)(row + 8) * N + col] = o1;
            }
        }
    }
}

extern "C" void kernel_launch(void* const* d_in, const int* in_sizes, int n_in,
                              void* d_out, int out_size)
{
    const float* x      = (const float*)d_in[0];
    const int*   qw     = (const int*)  d_in[1];
    const float* scales = (const float*)d_in[2];
    const float* bias   = (const float*)d_in[3];
    float*       out    = (float*)d_out;

    const int O  = in_sizes[3];            // 8192
    const int NB = in_sizes[2] / O;        // 256
    const int K  = NB * 32;                // 8192
    const int M  = in_sizes[0] / K;        // 4096
    const int N  = O;

    // pre-passes: x -> fp16, W -> fp16
    cvt_kernel<<<1024, 256>>>(x, (size_t)M * K / 4);
    dq_kernel<<<2048, 256>>>(qw, scales, (size_t)O * NB);

    cudaFuncSetAttribute(q4_hmma_kernel, cudaFuncAttributeMaxDynamicSharedMemorySize,
                         SMEM_BYTES);
    dim3 grid(N / BN, M / BM);
    q4_hmma_kernel<<<grid, NTH, SMEM_BYTES>>>(bias, out, M, N, K);
}

// round 14
// speedup vs baseline: 1.8064x; 1.0596x over previous
#include <cuda_runtime.h>
#include <cuda_fp16.h>
#include <cstdint>

// Q4_0 dequant GEMM, R12: pre-dequantized fp16 W + clean HMMA GEMM.
// NTH=256 (8 warps, warp tile 64x32), 2 CTAs/SM -> 16 warps/SM (4/SMSP)
// to cover barrier + memory stalls that 2 warps/SMSP could not hide.

#define BM 128
#define BN 128
#define BK 64
#define NTH 256
#define ROWB 144                      // 16B-aligned; (9r+c)%8 = (r+c)%8 -> ldsm conflict-free
#define A_BYTES (128 * ROWB)          // 18432
#define B_OFF   A_BYTES
#define STAGE_BYTES (2 * A_BYTES)     // 36864
#define NSTAGE 3
#define SMEM_BYTES (NSTAGE * STAGE_BYTES)  // 110592

#define MCAP 4096
#define KCAP 8192
#define OCAP 8192
__device__ __half g_xh[(size_t)MCAP * KCAP];   // x  -> fp16
__device__ __half g_wh[(size_t)OCAP * KCAP];   // W  -> fp16 (dequantized)

__device__ __forceinline__ uint32_t smem_u32(const void* p) {
    uint32_t a;
    asm("{ .reg .u64 t; cvta.to.shared.u64 t, %1; cvt.u32.u64 %0, t; }" : "=r"(a) : "l"(p));
    return a;
}
__device__ __forceinline__ void ldsm4(uint32_t r[4], uint32_t addr) {
    asm volatile("ldmatrix.sync.aligned.m8n8.x4.shared.b16 {%0,%1,%2,%3}, [%4];"
                 : "=r"(r[0]), "=r"(r[1]), "=r"(r[2]), "=r"(r[3]) : "r"(addr));
}
__device__ __forceinline__ void mma16816(float c[4], const uint32_t a[4],
                                         uint32_t b0, uint32_t b1) {
    asm volatile("mma.sync.aligned.m16n8k16.row.col.f32.f16.f16.f32 "
                 "{%0,%1,%2,%3}, {%4,%5,%6,%7}, {%8,%9}, {%0,%1,%2,%3};"
                 : "+f"(c[0]), "+f"(c[1]), "+f"(c[2]), "+f"(c[3])
                 : "r"(a[0]), "r"(a[1]), "r"(a[2]), "r"(a[3]), "r"(b0), "r"(b1));
}
__device__ __forceinline__ uint32_t h2u(__half2 h) { return *reinterpret_cast<uint32_t*>(&h); }
__device__ __forceinline__ __half2 u2h(uint32_t u) { return *reinterpret_cast<__half2*>(&u); }

// ---- pre-pass 1: fp32 x -> fp16 ----
__global__ void cvt_kernel(const float* __restrict__ x, size_t n4) {
    size_t i = (size_t)blockIdx.x * blockDim.x + threadIdx.x;
    const size_t stride = (size_t)gridDim.x * blockDim.x;
    for (; i < n4; i += stride) {
        float4 v = ((const float4*)x)[i];
        __half2 h0 = __floats2half2_rn(v.x, v.y);
        __half2 h1 = __floats2half2_rn(v.z, v.w);
        uint2 u; u.x = h2u(h0); u.y = h2u(h1);
        ((uint2*)g_xh)[i] = u;
    }
}

// ---- pre-pass 2: Q4_0 -> fp16 W. One thread per 32-weight block. ----
__global__ void dq_kernel(const int* __restrict__ qw,
                          const float* __restrict__ scales, size_t nblk) {
    const uint32_t c1032 = 0x64086408u;    // half2(1032,1032); nib+1024-1032 = nib-8 exact
    size_t b = (size_t)blockIdx.x * blockDim.x + threadIdx.x;
    const size_t stride = (size_t)gridDim.x * blockDim.x;
    for (; b < nblk; b += stride) {
        const int4* qp = (const int4*)(qw + b * 16);
        int4 v0 = qp[0], v1 = qp[1], v2 = qp[2], v3 = qp[3];
        int q[16] = {v0.x, v0.y, v0.z, v0.w, v1.x, v1.y, v1.z, v1.w,
                     v2.x, v2.y, v2.z, v2.w, v3.x, v3.y, v3.z, v3.w};
        __half2 s2 = __half2half2(__float2half_rn(scales[b]));
        uint32_t w[16];
        #pragma unroll
        for (int j = 0; j < 8; ++j) {
            int q0 = q[2 * j], q1 = q[2 * j + 1];
            uint32_t lo = (uint32_t)(q0 & 0xF) | (((uint32_t)(q1 & 0xF)) << 16) | 0x64006400u;
            uint32_t hi = (uint32_t)((q0 >> 4) & 0xF)
                          | (((uint32_t)((q1 >> 4) & 0xF)) << 16) | 0x64006400u;
            w[j]     = h2u(__hmul2(__hsub2(u2h(lo), u2h(c1032)), s2));
            w[8 + j] = h2u(__hmul2(__hsub2(u2h(hi), u2h(c1032)), s2));
        }
        uint4* op = (uint4*)(g_wh + b * 32);
        op[0] = make_uint4(w[0],  w[1],  w[2],  w[3]);
        op[1] = make_uint4(w[4],  w[5],  w[6],  w[7]);
        op[2] = make_uint4(w[8],  w[9],  w[10], w[11]);
        op[3] = make_uint4(w[12], w[13], w[14], w[15]);
    }
}

__global__ __launch_bounds__(NTH, 2)
void q4_hmma_kernel(const float* __restrict__ bias,
                    float* __restrict__ out,
                    int M, int N, int K)
{
    extern __shared__ __align__(128) char smem[];
    const uint32_t sbase = smem_u32(smem);

    const int tid  = threadIdx.x;
    const int lane = tid & 31;
    const int wid  = tid >> 5;
    const int bm   = blockIdx.y * BM;
    const int bn   = blockIdx.x * BN;
    const int NT   = K / BK;   // 128

    // 8 warps: 2 (m) x 4 (n), warp tile 64x32
    const int m_off = (wid & 1) * 64;
    const int n_off = (wid >> 1) * 32;

    const uint32_t aLd = (uint32_t)((m_off + (lane & 15)) * ROWB + (lane >> 4) * 16);
    const uint32_t bLd = (uint32_t)((n_off + (lane & 7) + ((lane & 16) ? 8 : 0)) * ROWB
                                    + ((lane >> 3) & 1) * 16);

    float acc[4][4][4];
    #pragma unroll
    for (int i = 0; i < 4; ++i)
        #pragma unroll
        for (int j = 0; j < 4; ++j)
            #pragma unroll
            for (int v = 0; v < 4; ++v) acc[i][j][v] = 0.0f;

    // A tile: 128 rows x 128B; B tile: 128 rows x 128B. 256 threads -> 4 ops each, 16B/op.
#define CPAB(KT)                                                                       \
    do {                                                                               \
        const uint32_t st = sbase + ((KT) % NSTAGE) * STAGE_BYTES;                     \
        const __half* gA = &g_xh[(size_t)bm * K + (size_t)(KT) * BK];                  \
        const __half* gB = &g_wh[(size_t)bn * K + (size_t)(KT) * BK];                  \
        _Pragma("unroll")                                                              \
        for (int i = 0; i < 4; ++i) {                                                  \
            int idx = tid + i * NTH, row = idx >> 3, c = idx & 7;                      \
            uint32_t d = st + (uint32_t)(row * ROWB + c * 16);                         \
            const void* s = gA + (size_t)row * K + c * 8;                              \
            asm volatile("cp.async.cg.shared.global [%0], [%1], 16;" :: "r"(d), "l"(s)); \
        }                                                                              \
        _Pragma("unroll")                                                              \
        for (int i = 0; i < 4; ++i) {                                                  \
            int idx = tid + i * NTH, row = idx >> 3, c = idx & 7;                      \
            uint32_t d = st + B_OFF + (uint32_t)(row * ROWB + c * 16);                 \
            const void* s = gB + (size_t)row * K + c * 8;                              \
            asm volatile("cp.async.cg.shared.global [%0], [%1], 16;" :: "r"(d), "l"(s)); \
        }                                                                              \
        asm volatile("cp.async.commit_group;");                                        \
    } while (0)

    // prologue: stages 0, 1
    CPAB(0);
    CPAB(1);

    for (int kt = 0; kt < NT; ++kt) {
        if (kt + 1 < NT) {
            asm volatile("cp.async.wait_group 1;" ::: "memory");
        } else {
            asm volatile("cp.async.wait_group 0;" ::: "memory");
        }
        __syncthreads();   // all warps done with MMA(kt-1) -> stage (kt+2)%3 free

        const int k2 = kt + 2;
        if (k2 < NT) CPAB(k2);

        // ---- MMA on stage kt ----
        {
            const uint32_t st = sbase + (kt % NSTAGE) * STAGE_BYTES;
            const uint32_t aB = st + aLd;
            const uint32_t bB = st + B_OFF + bLd;
            #pragma unroll
            for (int ks = 0; ks < 4; ++ks) {
                uint32_t a[4][4];
                #pragma unroll
                for (int mf = 0; mf < 4; ++mf)
                    ldsm4(a[mf], aB + (uint32_t)(mf * 16 * ROWB + ks * 32));
                uint32_t b[2][4];
                #pragma unroll
                for (int np = 0; np < 2; ++np)
                    ldsm4(b[np], bB + (uint32_t)(np * 16 * ROWB + ks * 32));
                #pragma unroll
                for (int mf = 0; mf < 4; ++mf)
                    #pragma unroll
                    for (int nf = 0; nf < 4; ++nf)
                        mma16816(acc[mf][nf], a[mf], b[nf >> 1][(nf & 1) * 2],
                                 b[nf >> 1][(nf & 1) * 2 + 1]);
            }
        }
    }

    // ---- epilogue: bias + store ----
    {
        const int g = lane >> 2, t = lane & 3;
        #pragma unroll
        for (int nf = 0; nf < 4; ++nf) {
            const int col = bn + n_off + nf * 8 + 2 * t;
            const float2 bb = *(const float2*)&bias[col];
            #pragma unroll
            for (int mf = 0; mf < 4; ++mf) {
                const int row = bm + m_off + mf * 16 + g;
                float2 o0, o1;
                o0.x = acc[mf][nf][0] + bb.x;
                o0.y = acc[mf][nf][1] + bb.y;
                o1.x = acc[mf][nf][2] + bb.x;
                o1.y = acc[mf][nf][3] + bb.y;
                *(float2*)&out[(size_t)row * N + col]       = o0;
                *(float2*)&out[(size_t)(row + 8) * N + col] = o1;
            }
        }
    }
}

extern "C" void kernel_launch(void* const* d_in, const int* in_sizes, int n_in,
                              void* d_out, int out_size)
{
    const float* x      = (const float*)d_in[0];
    const int*   qw     = (const int*)  d_in[1];
    const float* scales = (const float*)d_in[2];
    const float* bias   = (const float*)d_in[3];
    float*       out    = (float*)d_out;

    const int O  = in_sizes[3];            // 8192
    const int NB = in_sizes[2] / O;        // 256
    const int K  = NB * 32;                // 8192
    const int M  = in_sizes[0] / K;        // 4096
    const int N  = O;

    // pre-passes: x -> fp16, W -> fp16
    cvt_kernel<<<1024, 256>>>(x, (size_t)M * K / 4);
    dq_kernel<<<2048, 256>>>(qw, scales, (size_t)O * NB);

    cudaFuncSetAttribute(q4_hmma_kernel, cudaFuncAttributeMaxDynamicSharedMemorySize,
                         SMEM_BYTES);
    dim3 grid(N / BN, M / BM);
    q4_hmma_kernel<<<grid, NTH, SMEM_BYTES>>>(bias, out, M, N, K);
}

// round 16
// speedup vs baseline: 1.8889x; 1.0457x over previous
#include <cuda_runtime.h>
#include <cuda_fp16.h>
#include <cstdint>

// Q4_0 dequant GEMM, R15: pre-dequantized fp16 W + HMMA GEMM.
// Warp tile 64x64 (1.5x less ldsm bytes/MAC -> smem crossbar below tensor
// floor), NTH=128 (4 warps), NSTAGE=2, 3 CTAs/SM (12 warps, 3 barrier domains).

#define BM 128
#define BN 128
#define BK 64
#define NTH 128
#define ROWB 144                      // 16B-aligned; (9r+c)%8 = (r+c)%8 -> ldsm conflict-free
#define A_BYTES (128 * ROWB)          // 18432
#define B_OFF   A_BYTES
#define STAGE_BYTES (2 * A_BYTES)     // 36864
#define NSTAGE 2
#define SMEM_BYTES (NSTAGE * STAGE_BYTES)  // 73728

#define MCAP 4096
#define KCAP 8192
#define OCAP 8192
__device__ __half g_xh[(size_t)MCAP * KCAP];   // x  -> fp16
__device__ __half g_wh[(size_t)OCAP * KCAP];   // W  -> fp16 (dequantized)

__device__ __forceinline__ uint32_t smem_u32(const void* p) {
    uint32_t a;
    asm("{ .reg .u64 t; cvta.to.shared.u64 t, %1; cvt.u32.u64 %0, t; }" : "=r"(a) : "l"(p));
    return a;
}
__device__ __forceinline__ void ldsm4(uint32_t r[4], uint32_t addr) {
    asm volatile("ldmatrix.sync.aligned.m8n8.x4.shared.b16 {%0,%1,%2,%3}, [%4];"
                 : "=r"(r[0]), "=r"(r[1]), "=r"(r[2]), "=r"(r[3]) : "r"(addr));
}
__device__ __forceinline__ void mma16816(float c[4], const uint32_t a[4],
                                         uint32_t b0, uint32_t b1) {
    asm volatile("mma.sync.aligned.m16n8k16.row.col.f32.f16.f16.f32 "
                 "{%0,%1,%2,%3}, {%4,%5,%6,%7}, {%8,%9}, {%0,%1,%2,%3};"
                 : "+f"(c[0]), "+f"(c[1]), "+f"(c[2]), "+f"(c[3])
                 : "r"(a[0]), "r"(a[1]), "r"(a[2]), "r"(a[3]), "r"(b0), "r"(b1));
}
__device__ __forceinline__ uint32_t h2u(__half2 h) { return *reinterpret_cast<uint32_t*>(&h); }
__device__ __forceinline__ __half2 u2h(uint32_t u) { return *reinterpret_cast<__half2*>(&u); }

// ---- pre-pass 1: fp32 x -> fp16 ----
__global__ void cvt_kernel(const float* __restrict__ x, size_t n4) {
    size_t i = (size_t)blockIdx.x * blockDim.x + threadIdx.x;
    const size_t stride = (size_t)gridDim.x * blockDim.x;
    for (; i < n4; i += stride) {
        float4 v = ((const float4*)x)[i];
        __half2 h0 = __floats2half2_rn(v.x, v.y);
        __half2 h1 = __floats2half2_rn(v.z, v.w);
        uint2 u; u.x = h2u(h0); u.y = h2u(h1);
        ((uint2*)g_xh)[i] = u;
    }
}

// ---- pre-pass 2: Q4_0 -> fp16 W. One thread per 32-weight block. ----
__global__ void dq_kernel(const int* __restrict__ qw,
                          const float* __restrict__ scales, size_t nblk) {
    const uint32_t c1032 = 0x64086408u;    // half2(1032,1032); nib+1024-1032 = nib-8 exact
    size_t b = (size_t)blockIdx.x * blockDim.x + threadIdx.x;
    const size_t stride = (size_t)gridDim.x * blockDim.x;
    for (; b < nblk; b += stride) {
        const int4* qp = (const int4*)(qw + b * 16);
        int4 v0 = qp[0], v1 = qp[1], v2 = qp[2], v3 = qp[3];
        int q[16] = {v0.x, v0.y, v0.z, v0.w, v1.x, v1.y, v1.z, v1.w,
                     v2.x, v2.y, v2.z, v2.w, v3.x, v3.y, v3.z, v3.w};
        __half2 s2 = __half2half2(__float2half_rn(scales[b]));
        uint32_t w[16];
        #pragma unroll
        for (int j = 0; j < 8; ++j) {
            int q0 = q[2 * j], q1 = q[2 * j + 1];
            uint32_t lo = (uint32_t)(q0 & 0xF) | (((uint32_t)(q1 & 0xF)) << 16) | 0x64006400u;
            uint32_t hi = (uint32_t)((q0 >> 4) & 0xF)
                          | (((uint32_t)((q1 >> 4) & 0xF)) << 16) | 0x64006400u;
            w[j]     = h2u(__hmul2(__hsub2(u2h(lo), u2h(c1032)), s2));
            w[8 + j] = h2u(__hmul2(__hsub2(u2h(hi), u2h(c1032)), s2));
        }
        uint4* op = (uint4*)(g_wh + b * 32);
        op[0] = make_uint4(w[0],  w[1],  w[2],  w[3]);
        op[1] = make_uint4(w[4],  w[5],  w[6],  w[7]);
        op[2] = make_uint4(w[8],  w[9],  w[10], w[11]);
        op[3] = make_uint4(w[12], w[13], w[14], w[15]);
    }
}

__global__ __launch_bounds__(NTH, 3)
void q4_hmma_kernel(const float* __restrict__ bias,
                    float* __restrict__ out,
                    int M, int N, int K)
{
    extern __shared__ __align__(128) char smem[];
    const uint32_t sbase = smem_u32(smem);

    const int tid  = threadIdx.x;
    const int lane = tid & 31;
    const int wid  = tid >> 5;
    const int bm   = blockIdx.y * BM;
    const int bn   = blockIdx.x * BN;
    const int NT   = K / BK;   // 128

    // 4 warps: 2 (m) x 2 (n), warp tile 64x64
    const int m_off = (wid & 1) * 64;
    const int n_off = (wid >> 1) * 64;

    const uint32_t aLd = (uint32_t)((m_off + (lane & 15)) * ROWB + (lane >> 4) * 16);
    const uint32_t bLd = (uint32_t)((n_off + (lane & 7) + ((lane & 16) ? 8 : 0)) * ROWB
                                    + ((lane >> 3) & 1) * 16);

    float acc[4][8][4];
    #pragma unroll
    for (int i = 0; i < 4; ++i)
        #pragma unroll
        for (int j = 0; j < 8; ++j)
            #pragma unroll
            for (int v = 0; v < 4; ++v) acc[i][j][v] = 0.0f;

    // A tile: 128 rows x 128B; B tile: same. 128 threads -> 8+8 cp.async, 16B each.
#define CPAB(KT)                                                                       \
    do {                                                                               \
        const uint32_t st = sbase + ((KT) & 1) * STAGE_BYTES;                          \
        const __half* gA = &g_xh[(size_t)bm * K + (size_t)(KT) * BK];                  \
        const __half* gB = &g_wh[(size_t)bn * K + (size_t)(KT) * BK];                  \
        _Pragma("unroll")                                                              \
        for (int i = 0; i < 8; ++i) {                                                  \
            int idx = tid + i * NTH, row = idx >> 3, c = idx & 7;                      \
            uint32_t d = st + (uint32_t)(row * ROWB + c * 16);                         \
            const void* s = gA + (size_t)row * K + c * 8;                              \
            asm volatile("cp.async.cg.shared.global [%0], [%1], 16;" :: "r"(d), "l"(s)); \
        }                                                                              \
        _Pragma("unroll")                                                              \
        for (int i = 0; i < 8; ++i) {                                                  \
            int idx = tid + i * NTH, row = idx >> 3, c = idx & 7;                      \
            uint32_t d = st + B_OFF + (uint32_t)(row * ROWB + c * 16);                 \
            const void* s = gB + (size_t)row * K + c * 8;                              \
            asm volatile("cp.async.cg.shared.global [%0], [%1], 16;" :: "r"(d), "l"(s)); \
        }                                                                              \
        asm volatile("cp.async.commit_group;");                                        \
    } while (0)

    // prologue: stage 0 in flight
    CPAB(0);

    for (int kt = 0; kt < NT; ++kt) {
        asm volatile("cp.async.wait_group 0;" ::: "memory");  // stage kt landed
        __syncthreads();   // all warps done with MMA(kt-1) -> other buffer free

        const int kn = kt + 1;
        if (kn < NT) CPAB(kn);   // fills other buffer while MMA(kt) runs

        // ---- MMA on stage kt ----
        {
            const uint32_t st = sbase + (kt & 1) * STAGE_BYTES;
            const uint32_t aB = st + aLd;
            const uint32_t bB = st + B_OFF + bLd;
            #pragma unroll
            for (int ks = 0; ks < 4; ++ks) {
                uint32_t a[4][4];
                #pragma unroll
                for (int mf = 0; mf < 4; ++mf)
                    ldsm4(a[mf], aB + (uint32_t)(mf * 16 * ROWB + ks * 32));
                uint32_t b[4][4];
                #pragma unroll
                for (int np = 0; np < 4; ++np)
                    ldsm4(b[np], bB + (uint32_t)(np * 16 * ROWB + ks * 32));
                #pragma unroll
                for (int mf = 0; mf < 4; ++mf)
                    #pragma unroll
                    for (int nf = 0; nf < 8; ++nf)
                        mma16816(acc[mf][nf], a[mf], b[nf >> 1][(nf & 1) * 2],
                                 b[nf >> 1][(nf & 1) * 2 + 1]);
            }
        }
    }

    // ---- epilogue: bias + store ----
    {
        const int g = lane >> 2, t = lane & 3;
        #pragma unroll
        for (int nf = 0; nf < 8; ++nf) {
            const int col = bn + n_off + nf * 8 + 2 * t;
            const float2 bb = *(const float2*)&bias[col];
            #pragma unroll
            for (int mf = 0; mf < 4; ++mf) {
                const int row = bm + m_off + mf * 16 + g;
                float2 o0, o1;
                o0.x = acc[mf][nf][0] + bb.x;
                o0.y = acc[mf][nf][1] + bb.y;
                o1.x = acc[mf][nf][2] + bb.x;
                o1.y = acc[mf][nf][3] + bb.y;
                *(float2*)&out[(size_t)row * N + col]       = o0;
                *(float2*)&out[(size_t)(row + 8) * N + col] = o1;
            }
        }
    }
}

extern "C" void kernel_launch(void* const* d_in, const int* in_sizes, int n_in,
                              void* d_out, int out_size)
{
    const float* x      = (const float*)d_in[0];
    const int*   qw     = (const int*)  d_in[1];
    const float* scales = (const float*)d_in[2];
    const float* bias   = (const float*)d_in[3];
    float*       out    = (float*)d_out;

    const int O  = in_sizes[3];            // 8192
    const int NB = in_sizes[2] / O;        // 256
    const int K  = NB * 32;                // 8192
    const int M  = in_sizes[0] / K;        // 4096
    const int N  = O;

    // pre-passes: x -> fp16, W -> fp16
    cvt_kernel<<<1024, 256>>>(x, (size_t)M * K / 4);
    dq_kernel<<<2048, 256>>>(qw, scales, (size_t)O * NB);

    cudaFuncSetAttribute(q4_hmma_kernel, cudaFuncAttributeMaxDynamicSharedMemorySize,
                         SMEM_BYTES);
    dim3 grid(N / BN, M / BM);
    q4_hmma_kernel<<<grid, NTH, SMEM_BYTES>>>(bias, out, M, N, K);
}

// round 17
// speedup vs baseline: 1.9169x; 1.0148x over previous
#include <cuda_runtime.h>
#include <cuda_fp16.h>
#include <cstdint>

// Q4_0 dequant GEMM, R17: R16 GEMM core (64x64 warp tiles, NSTAGE=2,
// 3 CTAs/SM) + persistent tile loop (no wave quantization) + merged pre-pass.

#define BM 128
#define BN 128
#define BK 64
#define NTH 128
#define ROWB 144                      // 16B-aligned; (9r+c)%8 = (r+c)%8 -> ldsm conflict-free
#define A_BYTES (128 * ROWB)          // 18432
#define B_OFF   A_BYTES
#define STAGE_BYTES (2 * A_BYTES)     // 36864
#define NSTAGE 2
#define SMEM_BYTES (NSTAGE * STAGE_BYTES)  // 73728

#define MCAP 4096
#define KCAP 8192
#define OCAP 8192
__device__ __half g_xh[(size_t)MCAP * KCAP];   // x  -> fp16
__device__ __half g_wh[(size_t)OCAP * KCAP];   // W  -> fp16 (dequantized)

__device__ __forceinline__ uint32_t smem_u32(const void* p) {
    uint32_t a;
    asm("{ .reg .u64 t; cvta.to.shared.u64 t, %1; cvt.u32.u64 %0, t; }" : "=r"(a) : "l"(p));
    return a;
}
__device__ __forceinline__ void ldsm4(uint32_t r[4], uint32_t addr) {
    asm volatile("ldmatrix.sync.aligned.m8n8.x4.shared.b16 {%0,%1,%2,%3}, [%4];"
                 : "=r"(r[0]), "=r"(r[1]), "=r"(r[2]), "=r"(r[3]) : "r"(addr));
}
__device__ __forceinline__ void mma16816(float c[4], const uint32_t a[4],
                                         uint32_t b0, uint32_t b1) {
    asm volatile("mma.sync.aligned.m16n8k16.row.col.f32.f16.f16.f32 "
                 "{%0,%1,%2,%3}, {%4,%5,%6,%7}, {%8,%9}, {%0,%1,%2,%3};"
                 : "+f"(c[0]), "+f"(c[1]), "+f"(c[2]), "+f"(c[3])
                 : "r"(a[0]), "r"(a[1]), "r"(a[2]), "r"(a[3]), "r"(b0), "r"(b1));
}
__device__ __forceinline__ uint32_t h2u(__half2 h) { return *reinterpret_cast<uint32_t*>(&h); }
__device__ __forceinline__ __half2 u2h(uint32_t u) { return *reinterpret_cast<__half2*>(&u); }

// ---- merged pre-pass: x -> fp16 AND Q4_0 W -> fp16 in one launch ----
__global__ void prep_kernel(const float* __restrict__ x, size_t n4,
                            const int* __restrict__ qw,
                            const float* __restrict__ scales, size_t nblk)
{
    const size_t stride = (size_t)gridDim.x * blockDim.x;
    size_t i0 = (size_t)blockIdx.x * blockDim.x + threadIdx.x;

    for (size_t i = i0; i < n4; i += stride) {
        float4 v = ((const float4*)x)[i];
        __half2 h0 = __floats2half2_rn(v.x, v.y);
        __half2 h1 = __floats2half2_rn(v.z, v.w);
        uint2 u; u.x = h2u(h0); u.y = h2u(h1);
        ((uint2*)g_xh)[i] = u;
    }

    const uint32_t c1032 = 0x64086408u;    // half2(1032,1032); nib+1024-1032 = nib-8 exact
    for (size_t b = i0; b < nblk; b += stride) {
        const int4* qp = (const int4*)(qw + b * 16);
        int4 v0 = qp[0], v1 = qp[1], v2 = qp[2], v3 = qp[3];
        int q[16] = {v0.x, v0.y, v0.z, v0.w, v1.x, v1.y, v1.z, v1.w,
                     v2.x, v2.y, v2.z, v2.w, v3.x, v3.y, v3.z, v3.w};
        __half2 s2 = __half2half2(__float2half_rn(scales[b]));
        uint32_t w[16];
        #pragma unroll
        for (int j = 0; j < 8; ++j) {
            int q0 = q[2 * j], q1 = q[2 * j + 1];
            uint32_t lo = (uint32_t)(q0 & 0xF) | (((uint32_t)(q1 & 0xF)) << 16) | 0x64006400u;
            uint32_t hi = (uint32_t)((q0 >> 4) & 0xF)
                          | (((uint32_t)((q1 >> 4) & 0xF)) << 16) | 0x64006400u;
            w[j]     = h2u(__hmul2(__hsub2(u2h(lo), u2h(c1032)), s2));
            w[8 + j] = h2u(__hmul2(__hsub2(u2h(hi), u2h(c1032)), s2));
        }
        uint4* op = (uint4*)(g_wh + b * 32);
        op[0] = make_uint4(w[0],  w[1],  w[2],  w[3]);
        op[1] = make_uint4(w[4],  w[5],  w[6],  w[7]);
        op[2] = make_uint4(w[8],  w[9],  w[10], w[11]);
        op[3] = make_uint4(w[12], w[13], w[14], w[15]);
    }
}

__global__ __launch_bounds__(NTH, 3)
void q4_hmma_kernel(const float* __restrict__ bias,
                    float* __restrict__ out,
                    int M, int N, int K, int nTiles)
{
    extern __shared__ __align__(128) char smem[];
    const uint32_t sbase = smem_u32(smem);

    const int tid  = threadIdx.x;
    const int lane = tid & 31;
    const int wid  = tid >> 5;
    const int NT   = K / BK;          // 128
    const int nTx  = N / BN;          // 64

    // 4 warps: 2 (m) x 2 (n), warp tile 64x64
    const int m_off = (wid & 1) * 64;
    const int n_off = (wid >> 1) * 64;

    const uint32_t aLd = (uint32_t)((m_off + (lane & 15)) * ROWB + (lane >> 4) * 16);
    const uint32_t bLd = (uint32_t)((n_off + (lane & 7) + ((lane & 16) ? 8 : 0)) * ROWB
                                    + ((lane >> 3) & 1) * 16);

#define CPAB(KT)                                                                       \
    do {                                                                               \
        const uint32_t st = sbase + ((KT) & 1) * STAGE_BYTES;                          \
        const __half* gA = &g_xh[(size_t)bm * K + (size_t)(KT) * BK];                  \
        const __half* gB = &g_wh[(size_t)bn * K + (size_t)(KT) * BK];                  \
        _Pragma("unroll")                                                              \
        for (int i = 0; i < 8; ++i) {                                                  \
            int idx = tid + i * NTH, row = idx >> 3, c = idx & 7;                      \
            uint32_t d = st + (uint32_t)(row * ROWB + c * 16);                         \
            const void* s = gA + (size_t)row * K + c * 8;                              \
            asm volatile("cp.async.cg.shared.global [%0], [%1], 16;" :: "r"(d), "l"(s)); \
        }                                                                              \
        _Pragma("unroll")                                                              \
        for (int i = 0; i < 8; ++i) {                                                  \
            int idx = tid + i * NTH, row = idx >> 3, c = idx & 7;                      \
            uint32_t d = st + B_OFF + (uint32_t)(row * ROWB + c * 16);                 \
            const void* s = gB + (size_t)row * K + c * 8;                              \
            asm volatile("cp.async.cg.shared.global [%0], [%1], 16;" :: "r"(d), "l"(s)); \
        }                                                                              \
        asm volatile("cp.async.commit_group;");                                        \
    } while (0)

    // ---- persistent tile loop ----
    for (int t = blockIdx.x; t < nTiles; t += gridDim.x) {
        const int bm = (t / nTx) * BM;
        const int bn = (t % nTx) * BN;

        float acc[4][8][4];
        #pragma unroll
        for (int i = 0; i < 4; ++i)
            #pragma unroll
            for (int j = 0; j < 8; ++j)
                #pragma unroll
                for (int v = 0; v < 4; ++v) acc[i][j][v] = 0.0f;

        __syncthreads();   // previous tile's MMA fully done before refilling stage 0
        CPAB(0);

        for (int kt = 0; kt < NT; ++kt) {
            asm volatile("cp.async.wait_group 0;" ::: "memory");  // stage kt landed
            __syncthreads();   // all warps done with MMA(kt-1) -> other buffer free

            const int kn = kt + 1;
            if (kn < NT) CPAB(kn);   // fills other buffer while MMA(kt) runs

            // ---- MMA on stage kt ----
            {
                const uint32_t st = sbase + (kt & 1) * STAGE_BYTES;
                const uint32_t aB = st + aLd;
                const uint32_t bB = st + B_OFF + bLd;
                #pragma unroll
                for (int ks = 0; ks < 4; ++ks) {
                    uint32_t a[4][4];
                    #pragma unroll
                    for (int mf = 0; mf < 4; ++mf)
                        ldsm4(a[mf], aB + (uint32_t)(mf * 16 * ROWB + ks * 32));
                    uint32_t b[4][4];
                    #pragma unroll
                    for (int np = 0; np < 4; ++np)
                        ldsm4(b[np], bB + (uint32_t)(np * 16 * ROWB + ks * 32));
                    #pragma unroll
                    for (int mf = 0; mf < 4; ++mf)
                        #pragma unroll
                        for (int nf = 0; nf < 8; ++nf)
                            mma16816(acc[mf][nf], a[mf], b[nf >> 1][(nf & 1) * 2],
                                     b[nf >> 1][(nf & 1) * 2 + 1]);
                }
            }
        }

        // ---- epilogue: bias + store ----
        {
            const int g = lane >> 2, tt = lane & 3;
            #pragma unroll
            for (int nf = 0; nf < 8; ++nf) {
                const int col = bn + n_off + nf * 8 + 2 * tt;
                const float2 bb = *(const float2*)&bias[col];
                #pragma unroll
                for (int mf = 0; mf < 4; ++mf) {
                    const int row = bm + m_off + mf * 16 + g;
                    float2 o0, o1;
                    o0.x = acc[mf][nf][0] + bb.x;
                    o0.y = acc[mf][nf][1] + bb.y;
                    o1.x = acc[mf][nf][2] + bb.x;
                    o1.y = acc[mf][nf][3] + bb.y;
                    *(float2*)&out[(size_t)row * N + col]       = o0;
                    *(float2*)&out[(size_t)(row + 8) * N + col] = o1;
                }
            }
        }
    }
}

extern "C" void kernel_launch(void* const* d_in, const int* in_sizes, int n_in,
                              void* d_out, int out_size)
{
    const float* x      = (const float*)d_in[0];
    const int*   qw     = (const int*)  d_in[1];
    const float* scales = (const float*)d_in[2];
    const float* bias   = (const float*)d_in[3];
    float*       out    = (float*)d_out;

    const int O  = in_sizes[3];            // 8192
    const int NB = in_sizes[2] / O;        // 256
    const int K  = NB * 32;                // 8192
    const int M  = in_sizes[0] / K;        // 4096
    const int N  = O;
    const int nTiles = (M / BM) * (N / BN);   // 2048

    // merged pre-pass: x -> fp16 and W -> fp16
    prep_kernel<<<2048, 256>>>(x, (size_t)M * K / 4, qw, scales, (size_t)O * NB);

    // persistent grid: 3 CTAs per SM, no wave quantization
    int nsm = 148;
    cudaDeviceGetAttribute(&nsm, cudaDevAttrMultiProcessorCount, 0);
    int grid = nsm * 3;
    if (grid > nTiles) grid = nTiles;

    cudaFuncSetAttribute(q4_hmma_kernel, cudaFuncAttributeMaxDynamicSharedMemorySize,
                         SMEM_BYTES);
    q4_hmma_kernel<<<grid, NTH, SMEM_BYTES>>>(bias, out, M, N, K, nTiles);
}